// round 14
// baseline (speedup 1.0000x reference)
#include <cuda_runtime.h>
#include <cuda_fp16.h>
#include <math.h>
#include <cstdint>

#define BB 2
#define SS 2048
#define DD 1024
#define HH 16
#define HDIM 64
#define DFF 4096
#define MROWS (BB * SS)

// ---------------- PTX helpers ----------------
__device__ __forceinline__ uint32_t smem_to_u32(const void* p) {
    uint32_t a;
    asm("{ .reg .u64 t; cvta.to.shared.u64 t, %1; cvt.u32.u64 %0, t; }" : "=r"(a) : "l"(p));
    return a;
}
__device__ __forceinline__ void ldmx4(uint32_t* r, uint32_t a) {
    asm volatile("ldmatrix.sync.aligned.m8n8.x4.shared.b16 {%0,%1,%2,%3}, [%4];"
        : "=r"(r[0]), "=r"(r[1]), "=r"(r[2]), "=r"(r[3]) : "r"(a));
}
__device__ __forceinline__ void ldmx4t(uint32_t* r, uint32_t a) {
    asm volatile("ldmatrix.sync.aligned.m8n8.x4.trans.shared.b16 {%0,%1,%2,%3}, [%4];"
        : "=r"(r[0]), "=r"(r[1]), "=r"(r[2]), "=r"(r[3]) : "r"(a));
}
__device__ __forceinline__ void mma_f16(float* c, const uint32_t* a, uint32_t b0, uint32_t b1) {
    asm volatile("mma.sync.aligned.m16n8k16.row.col.f32.f16.f16.f32 "
        "{%0,%1,%2,%3}, {%4,%5,%6,%7}, {%8,%9}, {%0,%1,%2,%3};"
        : "+f"(c[0]), "+f"(c[1]), "+f"(c[2]), "+f"(c[3])
        : "r"(a[0]), "r"(a[1]), "r"(a[2]), "r"(a[3]), "r"(b0), "r"(b1));
}
#define CP_ASYNC16(s, g) asm volatile("cp.async.cg.shared.global [%0], [%1], 16;" :: "r"(s), "l"(g))
#define CP_ASYNC_COMMIT() asm volatile("cp.async.commit_group;" ::: "memory")
#define CP_ASYNC_WAIT1()  asm volatile("cp.async.wait_group 1;" ::: "memory")

__device__ __forceinline__ uint32_t swz(uint32_t row, uint32_t colbyte) {
    return row * 128 + (colbyte ^ ((row & 7) << 4));
}
__device__ __forceinline__ float gelu_exact(float v) {
    return 0.5f * v * (1.0f + erff(v * 0.70710678118654752f));
}

// ---------------- scratch ----------------
__device__ float g_x2[MROWS * DD];
__device__ __half g_h2 [MROWS * DD];
__device__ __half g_q  [MROWS * DD];
__device__ __half g_k  [MROWS * DD];
__device__ __half g_v  [MROWS * DD];
__device__ __half g_ctx[MROWS * DD];
__device__ __half g_mid[(size_t)MROWS * DFF];
__device__ __half g_wq[DD * DD], g_wk[DD * DD], g_wv[DD * DD], g_wo[DD * DD];
__device__ __half g_w1[(size_t)DD * DFF], g_w2[(size_t)DFF * DD];

// ---------------- fused weight transpose (all 6 weights, one launch) ----------------
__global__ void wsplit_all(const float* __restrict__ Wq, const float* __restrict__ Wk,
                           const float* __restrict__ Wv, const float* __restrict__ Wo,
                           const float* __restrict__ W1, const float* __restrict__ W2,
                           __half* __restrict__ Tq, __half* __restrict__ Tk,
                           __half* __restrict__ Tv, __half* __restrict__ To,
                           __half* __restrict__ T1, __half* __restrict__ T2) {
    int id = blockIdx.x;
    const float* W; __half* T; int K, N, bx, by;
    if (id < 4096) {
        int wi = id >> 10, rem = id & 1023;
        W = (wi == 0) ? Wq : (wi == 1) ? Wk : (wi == 2) ? Wv : Wo;
        T = (wi == 0) ? Tq : (wi == 1) ? Tk : (wi == 2) ? Tv : To;
        K = DD; N = DD; bx = rem & 31; by = rem >> 5;
    } else if (id < 8192) {
        int rem = id - 4096;
        W = W1; T = T1; K = DD; N = DFF; bx = rem & 127; by = rem >> 7;
    } else {
        int rem = id - 8192;
        W = W2; T = T2; K = DFF; N = DD; bx = rem & 31; by = rem >> 5;
    }
    __shared__ float tile[32][33];
    int tx = threadIdx.x, ty = threadIdx.y;
    #pragma unroll
    for (int i = 0; i < 4; i++)
        tile[ty + 8 * i][tx] = W[(size_t)(by * 32 + ty + 8 * i) * N + bx * 32 + tx];
    __syncthreads();
    #pragma unroll
    for (int i = 0; i < 4; i++) {
        float v = tile[tx][ty + 8 * i];
        T[(size_t)(bx * 32 + ty + 8 * i) * K + by * 32 + tx] = __float2half_rn(v);
    }
}

// ---------------- LayerNorm (fp16 out) ----------------
__global__ void ln_f16(const float* __restrict__ x, const float* __restrict__ gamma,
                       const float* __restrict__ beta, __half* __restrict__ y) {
    int row = blockIdx.x, tid = threadIdx.x;
    const float4 v = reinterpret_cast<const float4*>(x + (size_t)row * DD)[tid];
    float s = v.x + v.y + v.z + v.w;
    float sq = v.x * v.x + v.y * v.y + v.z * v.z + v.w * v.w;
    for (int o = 16; o > 0; o >>= 1) {
        s += __shfl_down_sync(0xffffffffu, s, o);
        sq += __shfl_down_sync(0xffffffffu, sq, o);
    }
    __shared__ float ws[8], wq[8];
    int lane = tid & 31, warp = tid >> 5;
    if (lane == 0) { ws[warp] = s; wq[warp] = sq; }
    __syncthreads();
    __shared__ float mu_s, rstd_s;
    if (tid == 0) {
        float ts = 0.f, tq = 0.f;
        #pragma unroll
        for (int i = 0; i < 8; i++) { ts += ws[i]; tq += wq[i]; }
        float mu = ts * (1.0f / DD);
        float var = tq * (1.0f / DD) - mu * mu;
        mu_s = mu; rstd_s = rsqrtf(var + 1e-5f);
    }
    __syncthreads();
    float mu = mu_s, r = rstd_s;
    float4 g4 = reinterpret_cast<const float4*>(gamma)[tid];
    float4 b4 = reinterpret_cast<const float4*>(beta)[tid];
    float o0 = (v.x - mu) * r * g4.x + b4.x;
    float o1 = (v.y - mu) * r * g4.y + b4.y;
    float o2 = (v.z - mu) * r * g4.z + b4.z;
    float o3 = (v.w - mu) * r * g4.w + b4.w;
    __half2 h0 = __floats2half2_rn(o0, o1);
    __half2 h1 = __floats2half2_rn(o2, o3);
    uint2 w = make_uint2(*reinterpret_cast<const uint32_t*>(&h0),
                         *reinterpret_cast<const uint32_t*>(&h1));
    *reinterpret_cast<uint2*>(y + (size_t)row * DD + tid * 4) = w;
}

// ---------------- GEMM core (fp16, 8 warps, 64x32 warp tile, 2 CTA/SM) ----------------
__device__ __forceinline__ void cpa_tile(uint32_t sdst, const __half* __restrict__ g,
                                         int K, int r0, int k0, int tid) {
    #pragma unroll
    for (int l = 0; l < 4; l++) {
        int f = tid + 256 * l;
        int row = f >> 3, c = f & 7;
        CP_ASYNC16(sdst + swz(row, c * 16), g + (size_t)(r0 + row) * K + k0 + c * 8);
    }
}

#define STAGE1 (2 * 16384)
#define GEMM_SMEM (3 * STAGE1)

__device__ __forceinline__ void gemm_core(const __half* __restrict__ A,
                                          const __half* __restrict__ B,
                                          float* __restrict__ C,
                                          __half* __restrict__ Ch,
                                          int N, int K,
                                          const float* __restrict__ bias,
                                          const float* __restrict__ res, int mode) {
    extern __shared__ char smem[];
    const uint32_t sb0 = smem_to_u32(smem);
    const int tid = threadIdx.x;
    const int wid = tid >> 5, lane = tid & 31;
    const int wm = wid >> 2, wn = wid & 3;      // 2x4 warp grid, warp tile 64x32
    const int m0 = blockIdx.y * 128, n0 = blockIdx.x * 128;
    const int lr = lane & 15, lc = lane >> 4;

    float acc[4][4][4];
    #pragma unroll
    for (int i = 0; i < 4; i++)
        #pragma unroll
        for (int j = 0; j < 4; j++)
            #pragma unroll
            for (int p = 0; p < 4; p++) acc[i][j][p] = 0.f;

    const int T = K >> 6;
    auto load_tile = [&](int t, int s) {
        uint32_t sb = sb0 + s * STAGE1;
        int k0 = t * 64;
        cpa_tile(sb,         A, K, m0, k0, tid);
        cpa_tile(sb + 16384, B, K, n0, k0, tid);
    };

    load_tile(0, 0);
    CP_ASYNC_COMMIT();
    load_tile(1, 1);
    CP_ASYNC_COMMIT();

    for (int t = 0; t < T; t++) {
        CP_ASYNC_WAIT1();
        __syncthreads();
        if (t + 2 < T) { load_tile(t + 2, (t + 2) % 3); CP_ASYNC_COMMIT(); }

        const uint32_t sb = sb0 + (t % 3) * STAGE1;
        const uint32_t sA = sb, sB = sb + 16384;
        #pragma unroll
        for (int kg = 0; kg < 4; kg++) {
            uint32_t af[4][4], bf[2][4];
            #pragma unroll
            for (int mt = 0; mt < 4; mt++)
                ldmx4(af[mt], sA + swz(wm * 64 + mt * 16 + lr, kg * 32 + lc * 16));
            #pragma unroll
            for (int np = 0; np < 2; np++)
                ldmx4(bf[np], sB + swz(wn * 32 + np * 16 + lr, kg * 32 + lc * 16));
            #pragma unroll
            for (int mt = 0; mt < 4; mt++) {
                #pragma unroll
                for (int nt = 0; nt < 4; nt++) {
                    int np = nt >> 1, u = nt & 1;
                    mma_f16(acc[mt][nt], af[mt], bf[np][u], bf[np][u + 2]);
                }
            }
        }
    }

    #pragma unroll
    for (int mt = 0; mt < 4; mt++) {
        #pragma unroll
        for (int nt = 0; nt < 4; nt++) {
            int r0 = m0 + wm * 64 + mt * 16 + (lane >> 2);
            int c0 = n0 + wn * 32 + nt * 8 + (lane & 3) * 2;
            float bv0 = 0.f, bv1 = 0.f;
            if (mode == 1 || mode == 2) { bv0 = bias[c0]; bv1 = bias[c0 + 1]; }
            #pragma unroll
            for (int half = 0; half < 2; half++) {
                int r = r0 + half * 8;
                float v0 = acc[mt][nt][half * 2 + 0] + bv0;
                float v1 = acc[mt][nt][half * 2 + 1] + bv1;
                if (mode == 3) {
                    __half2 hv = __floats2half2_rn(v0, v1);
                    *reinterpret_cast<uint32_t*>(Ch + (size_t)r * N + c0) =
                        *reinterpret_cast<const uint32_t*>(&hv);
                } else if (mode == 2) {
                    v0 = gelu_exact(v0); v1 = gelu_exact(v1);
                    __half2 hv = __floats2half2_rn(v0, v1);
                    *reinterpret_cast<uint32_t*>(Ch + (size_t)r * N + c0) =
                        *reinterpret_cast<const uint32_t*>(&hv);
                } else {
                    float2 rr = *(const float2*)(res + (size_t)r * N + c0);
                    *(float2*)(C + (size_t)r * N + c0) = make_float2(v0 + rr.x, v1 + rr.y);
                }
            }
        }
    }
}

__global__ void __launch_bounds__(256, 2)
gemm_qkv(const __half* __restrict__ A,
         const __half* __restrict__ wq, const __half* __restrict__ wk,
         const __half* __restrict__ wv,
         __half* __restrict__ q, __half* __restrict__ k, __half* __restrict__ v) {
    const __half* B = (blockIdx.z == 0) ? wq : (blockIdx.z == 1) ? wk : wv;
    __half* Ch = (blockIdx.z == 0) ? q : (blockIdx.z == 1) ? k : v;
    gemm_core(A, B, nullptr, Ch, DD, DD, nullptr, nullptr, 3);
}
__global__ void __launch_bounds__(256, 2)
gemm_f32(const __half* __restrict__ A, const __half* __restrict__ B,
         float* __restrict__ C, int N, int K,
         const float* __restrict__ bias, const float* __restrict__ res) {
    gemm_core(A, B, C, nullptr, N, K, bias, res, 1);
}
__global__ void __launch_bounds__(256, 2)
gemm_gelu(const __half* __restrict__ A, const __half* __restrict__ B,
          __half* __restrict__ Cf, int N, int K, const float* __restrict__ bias) {
    gemm_core(A, B, nullptr, Cf, N, K, bias, nullptr, 2);
}

// ---------------- Flash attention plain fp16 (unchanged) ----------------
#define AT_STAGE 16384
#define AT_SMEM (16384 + 2 * AT_STAGE)

__global__ void __launch_bounds__(256, 2)
attn_mma_kernel(const __half* __restrict__ q, const __half* __restrict__ k,
                const __half* __restrict__ v, __half* __restrict__ O) {
    extern __shared__ char smem[];
    const uint32_t sb = smem_to_u32(smem);
    const uint32_t sQ = sb;
    const int tid = threadIdx.x, wid = tid >> 5, lane = tid & 31;
    const int qt = blockIdx.x;
    const int h = blockIdx.y & 15, b = blockIdx.y >> 4;
    const size_t rowbase = (size_t)b * SS;
    const int colq = h * HDIM;

    #pragma unroll
    for (int l = 0; l < 4; l++) {
        int f = tid + 256 * l;
        int row = f >> 3, c = f & 7;
        CP_ASYNC16(sQ + swz(row, c * 16),
                   q + (rowbase + qt * 128 + row) * DD + colq + c * 8);
    }
    CP_ASYNC_COMMIT();

    auto load_kv = [&](int kt, int s) {
        uint32_t st = sb + 16384 + s * AT_STAGE;
        #pragma unroll
        for (int l = 0; l < 2; l++) {
            int f = tid + 256 * l;
            int row = f >> 3, c = f & 7;
            size_t g = (rowbase + kt * 64 + row) * DD + colq + c * 8;
            uint32_t o = swz(row, c * 16);
            CP_ASYNC16(st + o,        k + g);
            CP_ASYNC16(st + 8192 + o, v + g);
        }
    };
    load_kv(0, 0);
    CP_ASYNC_COMMIT();

    const int nkt = 2 * qt + 2;
    const int ktmax_w = (qt * 128 + wid * 16 + 15) >> 6;
    const int lr = lane & 15, lc = lane >> 4;
    const int r0l = lane >> 2;
    const int c2 = (lane & 3) * 2;
    const int rowg0 = qt * 128 + wid * 16 + r0l;

    float m_i[2] = {-1e30f, -1e30f}, l_i[2] = {0.f, 0.f};
    float oacc[8][4];
    #pragma unroll
    for (int i = 0; i < 8; i++)
        #pragma unroll
        for (int j = 0; j < 4; j++) oacc[i][j] = 0.f;

    for (int kt = 0; kt < nkt; kt++) {
        if (kt + 1 < nkt) load_kv(kt + 1, (kt + 1) & 1);
        CP_ASYNC_COMMIT();
        CP_ASYNC_WAIT1();
        __syncthreads();

        if (kt <= ktmax_w) {
            uint32_t st = sb + 16384 + (kt & 1) * AT_STAGE;
            uint32_t sK = st, sV = st + 8192;

            float sacc[8][4];
            #pragma unroll
            for (int i = 0; i < 8; i++)
                #pragma unroll
                for (int j = 0; j < 4; j++) sacc[i][j] = 0.f;

            #pragma unroll
            for (int kg = 0; kg < 4; kg++) {
                uint32_t a0[4];
                ldmx4(a0, sQ + swz(wid * 16 + lr, kg * 32 + lc * 16));
                #pragma unroll
                for (int np = 0; np < 4; np++) {
                    uint32_t b4[4];
                    ldmx4(b4, sK + swz(np * 16 + lr, kg * 32 + lc * 16));
                    mma_f16(sacc[np * 2],     a0, b4[0], b4[2]);
                    mma_f16(sacc[np * 2 + 1], a0, b4[1], b4[3]);
                }
            }

            float rm[2] = {-1e30f, -1e30f};
            #pragma unroll
            for (int nt = 0; nt < 8; nt++) {
                #pragma unroll
                for (int j = 0; j < 4; j++) {
                    int jr = j >> 1;
                    int rowg = rowg0 + jr * 8;
                    int colg = kt * 64 + nt * 8 + c2 + (j & 1);
                    float s = sacc[nt][j] * 0.125f;
                    if (colg > rowg) s = -1e30f;
                    sacc[nt][j] = s;
                    rm[jr] = fmaxf(rm[jr], s);
                }
            }
            #pragma unroll
            for (int jr = 0; jr < 2; jr++) {
                rm[jr] = fmaxf(rm[jr], __shfl_xor_sync(0xffffffffu, rm[jr], 1));
                rm[jr] = fmaxf(rm[jr], __shfl_xor_sync(0xffffffffu, rm[jr], 2));
            }
            float sc[2], rs[2] = {0.f, 0.f};
            #pragma unroll
            for (int jr = 0; jr < 2; jr++) {
                float mn = fmaxf(m_i[jr], rm[jr]);
                sc[jr] = __expf(m_i[jr] - mn);
                m_i[jr] = mn;
            }
            #pragma unroll
            for (int nt = 0; nt < 8; nt++) {
                #pragma unroll
                for (int j = 0; j < 4; j++) {
                    float p = __expf(sacc[nt][j] - m_i[j >> 1]);
                    sacc[nt][j] = p;
                    rs[j >> 1] += p;
                }
            }
            #pragma unroll
            for (int jr = 0; jr < 2; jr++) {
                rs[jr] += __shfl_xor_sync(0xffffffffu, rs[jr], 1);
                rs[jr] += __shfl_xor_sync(0xffffffffu, rs[jr], 2);
                l_i[jr] = l_i[jr] * sc[jr] + rs[jr];
            }
            #pragma unroll
            for (int nt = 0; nt < 8; nt++) {
                #pragma unroll
                for (int j = 0; j < 4; j++) oacc[nt][j] *= sc[j >> 1];
            }

            #pragma unroll
            for (int kc = 0; kc < 4; kc++) {
                uint32_t ph[4];
                __half2 p0 = __floats2half2_rn(sacc[2 * kc][0],     sacc[2 * kc][1]);
                __half2 p1 = __floats2half2_rn(sacc[2 * kc][2],     sacc[2 * kc][3]);
                __half2 p2 = __floats2half2_rn(sacc[2 * kc + 1][0], sacc[2 * kc + 1][1]);
                __half2 p3 = __floats2half2_rn(sacc[2 * kc + 1][2], sacc[2 * kc + 1][3]);
                ph[0] = *reinterpret_cast<const uint32_t*>(&p0);
                ph[1] = *reinterpret_cast<const uint32_t*>(&p1);
                ph[2] = *reinterpret_cast<const uint32_t*>(&p2);
                ph[3] = *reinterpret_cast<const uint32_t*>(&p3);
                uint32_t vrow = kc * 16 + ((lane >> 3) & 1) * 8 + (lane & 7);
                #pragma unroll
                for (int dp = 0; dp < 4; dp++) {
                    uint32_t v4[4];
                    ldmx4t(v4, sV + swz(vrow, dp * 32 + (lane >> 4) * 16));
                    mma_f16(oacc[dp * 2],     ph, v4[0], v4[1]);
                    mma_f16(oacc[dp * 2 + 1], ph, v4[2], v4[3]);
                }
            }
        }
        __syncthreads();
    }

    float inv[2] = {1.0f / l_i[0], 1.0f / l_i[1]};
    #pragma unroll
    for (int nt = 0; nt < 8; nt++) {
        #pragma unroll
        for (int jr = 0; jr < 2; jr++) {
            float v0 = oacc[nt][jr * 2 + 0] * inv[jr];
            float v1 = oacc[nt][jr * 2 + 1] * inv[jr];
            __half2 hv = __floats2half2_rn(v0, v1);
            size_t off = (rowbase + rowg0 + jr * 8) * DD + colq + nt * 8 + c2;
            *reinterpret_cast<uint32_t*>(O + off) = *reinterpret_cast<const uint32_t*>(&hv);
        }
    }
}

// ---------------- launch ----------------
extern "C" void kernel_launch(void* const* d_in, const int* in_sizes, int n_in,
                              void* d_out, int out_size) {
    const float* x     = (const float*)d_in[0];
    const float* ln1_g = (const float*)d_in[1];
    const float* ln1_b = (const float*)d_in[2];
    const float* Wq    = (const float*)d_in[3];
    const float* Wk    = (const float*)d_in[4];
    const float* Wv    = (const float*)d_in[5];
    const float* Wo    = (const float*)d_in[6];
    const float* bo    = (const float*)d_in[7];
    const float* ln2_g = (const float*)d_in[8];
    const float* ln2_b = (const float*)d_in[9];
    const float* W1    = (const float*)d_in[10];
    const float* b1    = (const float*)d_in[11];
    const float* W2    = (const float*)d_in[12];
    const float* b2    = (const float*)d_in[13];
    float* out = (float*)d_out;

    float* x2;
    cudaGetSymbolAddress((void**)&x2, g_x2);
    __half *h2, *q, *k, *v, *ctx, *mid;
    cudaGetSymbolAddress((void**)&h2, g_h2);
    cudaGetSymbolAddress((void**)&q, g_q);
    cudaGetSymbolAddress((void**)&k, g_k);
    cudaGetSymbolAddress((void**)&v, g_v);
    cudaGetSymbolAddress((void**)&ctx, g_ctx);
    cudaGetSymbolAddress((void**)&mid, g_mid);

    __half *wq, *wk, *wv, *wo, *w1, *w2;
    cudaGetSymbolAddress((void**)&wq, g_wq);
    cudaGetSymbolAddress((void**)&wk, g_wk);
    cudaGetSymbolAddress((void**)&wv, g_wv);
    cudaGetSymbolAddress((void**)&wo, g_wo);
    cudaGetSymbolAddress((void**)&w1, g_w1);
    cudaGetSymbolAddress((void**)&w2, g_w2);

    static int attr_set = 0;
    if (!attr_set) {
        cudaFuncSetAttribute(attn_mma_kernel, cudaFuncAttributeMaxDynamicSharedMemorySize, AT_SMEM);
        cudaFuncSetAttribute(gemm_qkv,  cudaFuncAttributeMaxDynamicSharedMemorySize, GEMM_SMEM);
        cudaFuncSetAttribute(gemm_f32,  cudaFuncAttributeMaxDynamicSharedMemorySize, GEMM_SMEM);
        cudaFuncSetAttribute(gemm_gelu, cudaFuncAttributeMaxDynamicSharedMemorySize, GEMM_SMEM);
        attr_set = 1;
    }

    const int M = MROWS;

    wsplit_all<<<12288, dim3(32, 8)>>>(Wq, Wk, Wv, Wo, W1, W2, wq, wk, wv, wo, w1, w2);

    ln_f16<<<M, 256>>>(x, ln1_g, ln1_b, h2);

    dim3 gQKV(DD / 128, M / 128, 3);
    gemm_qkv<<<gQKV, 256, GEMM_SMEM>>>(h2, wq, wk, wv, q, k, v);

    dim3 gA(SS / 128, BB * HH);
    attn_mma_kernel<<<gA, 256, AT_SMEM>>>(q, k, v, ctx);

    dim3 gDD(DD / 128, M / 128);
    gemm_f32<<<gDD, 256, GEMM_SMEM>>>(ctx, wo, x2, DD, DD, bo, x);

    ln_f16<<<M, 256>>>(x2, ln2_g, ln2_b, h2);

    dim3 gFF(DFF / 128, M / 128);
    gemm_gelu<<<gFF, 256, GEMM_SMEM>>>(h2, w1, mid, DFF, DD, b1);

    gemm_f32<<<gDD, 256, GEMM_SMEM>>>(mid, w2, out, DD, DFF, b2, x2);
}

// round 15
// speedup vs baseline: 1.0468x; 1.0468x over previous
#include <cuda_runtime.h>
#include <cuda_fp16.h>
#include <math.h>
#include <cstdint>

#define BB 2
#define SS 2048
#define DD 1024
#define HH 16
#define HDIM 64
#define DFF 4096
#define MROWS (BB * SS)

// ---------------- PTX helpers ----------------
__device__ __forceinline__ uint32_t smem_to_u32(const void* p) {
    uint32_t a;
    asm("{ .reg .u64 t; cvta.to.shared.u64 t, %1; cvt.u32.u64 %0, t; }" : "=r"(a) : "l"(p));
    return a;
}
__device__ __forceinline__ void ldmx4(uint32_t* r, uint32_t a) {
    asm volatile("ldmatrix.sync.aligned.m8n8.x4.shared.b16 {%0,%1,%2,%3}, [%4];"
        : "=r"(r[0]), "=r"(r[1]), "=r"(r[2]), "=r"(r[3]) : "r"(a));
}
__device__ __forceinline__ void ldmx4t(uint32_t* r, uint32_t a) {
    asm volatile("ldmatrix.sync.aligned.m8n8.x4.trans.shared.b16 {%0,%1,%2,%3}, [%4];"
        : "=r"(r[0]), "=r"(r[1]), "=r"(r[2]), "=r"(r[3]) : "r"(a));
}
__device__ __forceinline__ void mma_f16(float* c, const uint32_t* a, uint32_t b0, uint32_t b1) {
    asm volatile("mma.sync.aligned.m16n8k16.row.col.f32.f16.f16.f32 "
        "{%0,%1,%2,%3}, {%4,%5,%6,%7}, {%8,%9}, {%0,%1,%2,%3};"
        : "+f"(c[0]), "+f"(c[1]), "+f"(c[2]), "+f"(c[3])
        : "r"(a[0]), "r"(a[1]), "r"(a[2]), "r"(a[3]), "r"(b0), "r"(b1));
}
#define CP_ASYNC16(s, g) asm volatile("cp.async.cg.shared.global [%0], [%1], 16;" :: "r"(s), "l"(g))
#define CP_ASYNC_COMMIT() asm volatile("cp.async.commit_group;" ::: "memory")
#define CP_ASYNC_WAIT1()  asm volatile("cp.async.wait_group 1;" ::: "memory")

__device__ __forceinline__ uint32_t swz(uint32_t row, uint32_t colbyte) {
    return row * 128 + (colbyte ^ ((row & 7) << 4));
}
__device__ __forceinline__ float gelu_exact(float v) {
    return 0.5f * v * (1.0f + erff(v * 0.70710678118654752f));
}

// ---------------- scratch ----------------
__device__ float g_x2[MROWS * DD];
__device__ __half g_h2 [MROWS * DD];
__device__ __half g_q  [MROWS * DD];
__device__ __half g_k  [MROWS * DD];
__device__ __half g_v  [MROWS * DD];
__device__ __half g_ctx[MROWS * DD];
__device__ __half g_mid[(size_t)MROWS * DFF];
__device__ __half g_wq[DD * DD], g_wk[DD * DD], g_wv[DD * DD], g_wo[DD * DD];
__device__ __half g_w1[(size_t)DD * DFF], g_w2[(size_t)DFF * DD];

// ---------------- fast fused weight transpose: 64x64 tiles, float4 IO ----------------
// grid: 3072 blocks of 256 threads.
//   [0,1024):    Wq/Wk/Wv/Wo (256 tiles each), 16x16 tile grid
//   [1024,2048): W1 (K=1024,N=4096): bx in [0,64), by in [0,16)
//   [2048,3072): W2 (K=4096,N=1024): bx in [0,16), by in [0,64)
__global__ void __launch_bounds__(256)
wsplit_all(const float* __restrict__ Wq, const float* __restrict__ Wk,
           const float* __restrict__ Wv, const float* __restrict__ Wo,
           const float* __restrict__ W1, const float* __restrict__ W2,
           __half* __restrict__ Tq, __half* __restrict__ Tk,
           __half* __restrict__ Tv, __half* __restrict__ To,
           __half* __restrict__ T1, __half* __restrict__ T2) {
    int id = blockIdx.x;
    const float* W; __half* T; int K, N, bx, by;
    if (id < 1024) {
        int wi = id >> 8, rem = id & 255;
        W = (wi == 0) ? Wq : (wi == 1) ? Wk : (wi == 2) ? Wv : Wo;
        T = (wi == 0) ? Tq : (wi == 1) ? Tk : (wi == 2) ? Tv : To;
        K = DD; N = DD; bx = rem & 15; by = rem >> 4;
    } else if (id < 2048) {
        int rem = id - 1024;
        W = W1; T = T1; K = DD; N = DFF; bx = rem & 63; by = rem >> 6;
    } else {
        int rem = id - 2048;
        W = W2; T = T2; K = DFF; N = DD; bx = rem & 15; by = rem >> 4;
    }
    __shared__ float tile[64][65];
    int t = threadIdx.x;
    int tx = t & 15, ty = t >> 4;         // load: 16 float4 cols x 16 rows
    #pragma unroll
    for (int i = 0; i < 4; i++) {
        int row = ty + 16 * i;
        float4 v = *(const float4*)(W + (size_t)(by * 64 + row) * N + bx * 64 + tx * 4);
        tile[row][tx * 4 + 0] = v.x;
        tile[row][tx * 4 + 1] = v.y;
        tile[row][tx * 4 + 2] = v.z;
        tile[row][tx * 4 + 3] = v.w;
    }
    __syncthreads();
    // store transposed: out[n][k], 4 halves along k per store
    #pragma unroll
    for (int i = 0; i < 4; i++) {
        int n = ty + 16 * i;
        __half2 h0 = __floats2half2_rn(tile[tx * 4 + 0][n], tile[tx * 4 + 1][n]);
        __half2 h1 = __floats2half2_rn(tile[tx * 4 + 2][n], tile[tx * 4 + 3][n]);
        uint2 w = make_uint2(*reinterpret_cast<const uint32_t*>(&h0),
                             *reinterpret_cast<const uint32_t*>(&h1));
        *reinterpret_cast<uint2*>(T + (size_t)(bx * 64 + n) * K + by * 64 + tx * 4) = w;
    }
}

// ---------------- LayerNorm (fp16 out) ----------------
__global__ void ln_f16(const float* __restrict__ x, const float* __restrict__ gamma,
                       const float* __restrict__ beta, __half* __restrict__ y) {
    int row = blockIdx.x, tid = threadIdx.x;
    const float4 v = reinterpret_cast<const float4*>(x + (size_t)row * DD)[tid];
    float s = v.x + v.y + v.z + v.w;
    float sq = v.x * v.x + v.y * v.y + v.z * v.z + v.w * v.w;
    for (int o = 16; o > 0; o >>= 1) {
        s += __shfl_down_sync(0xffffffffu, s, o);
        sq += __shfl_down_sync(0xffffffffu, sq, o);
    }
    __shared__ float ws[8], wq[8];
    int lane = tid & 31, warp = tid >> 5;
    if (lane == 0) { ws[warp] = s; wq[warp] = sq; }
    __syncthreads();
    __shared__ float mu_s, rstd_s;
    if (tid == 0) {
        float ts = 0.f, tq = 0.f;
        #pragma unroll
        for (int i = 0; i < 8; i++) { ts += ws[i]; tq += wq[i]; }
        float mu = ts * (1.0f / DD);
        float var = tq * (1.0f / DD) - mu * mu;
        mu_s = mu; rstd_s = rsqrtf(var + 1e-5f);
    }
    __syncthreads();
    float mu = mu_s, r = rstd_s;
    float4 g4 = reinterpret_cast<const float4*>(gamma)[tid];
    float4 b4 = reinterpret_cast<const float4*>(beta)[tid];
    float o0 = (v.x - mu) * r * g4.x + b4.x;
    float o1 = (v.y - mu) * r * g4.y + b4.y;
    float o2 = (v.z - mu) * r * g4.z + b4.z;
    float o3 = (v.w - mu) * r * g4.w + b4.w;
    __half2 h0 = __floats2half2_rn(o0, o1);
    __half2 h1 = __floats2half2_rn(o2, o3);
    uint2 w = make_uint2(*reinterpret_cast<const uint32_t*>(&h0),
                         *reinterpret_cast<const uint32_t*>(&h1));
    *reinterpret_cast<uint2*>(y + (size_t)row * DD + tid * 4) = w;
}

// ---------------- GEMM core (R13 config: 4 warps, 64x64 warp tile, frag pipe) ----------------
__device__ __forceinline__ void cpa_tile(uint32_t sdst, const __half* __restrict__ g,
                                         int K, int r0, int k0, int tid) {
    #pragma unroll
    for (int l = 0; l < 8; l++) {
        int f = tid + 128 * l;
        int row = f >> 3, c = f & 7;
        CP_ASYNC16(sdst + swz(row, c * 16), g + (size_t)(r0 + row) * K + k0 + c * 8);
    }
}

#define STAGE1 (2 * 16384)
#define GEMM_SMEM (3 * STAGE1)

__device__ __forceinline__ void gemm_core(const __half* __restrict__ A,
                                          const __half* __restrict__ B,
                                          float* __restrict__ C,
                                          __half* __restrict__ Ch,
                                          int N, int K,
                                          const float* __restrict__ bias,
                                          const float* __restrict__ res, int mode) {
    extern __shared__ char smem[];
    const uint32_t sb0 = smem_to_u32(smem);
    const int tid = threadIdx.x;
    const int wid = tid >> 5, lane = tid & 31;
    const int wm = wid >> 1, wn = wid & 1;
    const int m0 = blockIdx.y * 128, n0 = blockIdx.x * 128;
    const int lr = lane & 15, lc = lane >> 4;

    float acc[4][8][4];
    #pragma unroll
    for (int i = 0; i < 4; i++)
        #pragma unroll
        for (int j = 0; j < 8; j++)
            #pragma unroll
            for (int p = 0; p < 4; p++) acc[i][j][p] = 0.f;

    const int T = K >> 6;
    auto load_tile = [&](int t, int s) {
        uint32_t sb = sb0 + s * STAGE1;
        int k0 = t * 64;
        cpa_tile(sb,         A, K, m0, k0, tid);
        cpa_tile(sb + 16384, B, K, n0, k0, tid);
    };

    load_tile(0, 0);
    CP_ASYNC_COMMIT();
    load_tile(1, 1);
    CP_ASYNC_COMMIT();

    uint32_t af[2][4][4], bf[2][4][4];

    for (int t = 0; t < T; t++) {
        CP_ASYNC_WAIT1();
        __syncthreads();
        if (t + 2 < T) { load_tile(t + 2, (t + 2) % 3); CP_ASYNC_COMMIT(); }

        const uint32_t sb = sb0 + (t % 3) * STAGE1;
        const uint32_t sA = sb, sB = sb + 16384;

        #pragma unroll
        for (int mt = 0; mt < 4; mt++)
            ldmx4(af[0][mt], sA + swz(wm * 64 + mt * 16 + lr, lc * 16));
        #pragma unroll
        for (int np = 0; np < 4; np++)
            ldmx4(bf[0][np], sB + swz(wn * 64 + np * 16 + lr, lc * 16));

        #pragma unroll
        for (int kg = 0; kg < 4; kg++) {
            const int cur = kg & 1, nxt = cur ^ 1;
            if (kg < 3) {
                #pragma unroll
                for (int mt = 0; mt < 4; mt++)
                    ldmx4(af[nxt][mt], sA + swz(wm * 64 + mt * 16 + lr, (kg + 1) * 32 + lc * 16));
                #pragma unroll
                for (int np = 0; np < 4; np++)
                    ldmx4(bf[nxt][np], sB + swz(wn * 64 + np * 16 + lr, (kg + 1) * 32 + lc * 16));
            }
            #pragma unroll
            for (int mt = 0; mt < 4; mt++) {
                #pragma unroll
                for (int np = 0; np < 4; np++) {
                    mma_f16(acc[mt][np * 2 + 0], af[cur][mt], bf[cur][np][0], bf[cur][np][2]);
                    mma_f16(acc[mt][np * 2 + 1], af[cur][mt], bf[cur][np][1], bf[cur][np][3]);
                }
            }
        }
    }

    #pragma unroll
    for (int mt = 0; mt < 4; mt++) {
        #pragma unroll
        for (int nt = 0; nt < 8; nt++) {
            int r0 = m0 + wm * 64 + mt * 16 + (lane >> 2);
            int c0 = n0 + wn * 64 + nt * 8 + (lane & 3) * 2;
            float bv0 = 0.f, bv1 = 0.f;
            if (mode == 1 || mode == 2) { bv0 = bias[c0]; bv1 = bias[c0 + 1]; }
            #pragma unroll
            for (int half = 0; half < 2; half++) {
                int r = r0 + half * 8;
                float v0 = acc[mt][nt][half * 2 + 0] + bv0;
                float v1 = acc[mt][nt][half * 2 + 1] + bv1;
                if (mode == 3) {
                    __half2 hv = __floats2half2_rn(v0, v1);
                    *reinterpret_cast<uint32_t*>(Ch + (size_t)r * N + c0) =
                        *reinterpret_cast<const uint32_t*>(&hv);
                } else if (mode == 2) {
                    v0 = gelu_exact(v0); v1 = gelu_exact(v1);
                    __half2 hv = __floats2half2_rn(v0, v1);
                    *reinterpret_cast<uint32_t*>(Ch + (size_t)r * N + c0) =
                        *reinterpret_cast<const uint32_t*>(&hv);
                } else {
                    float2 rr = *(const float2*)(res + (size_t)r * N + c0);
                    *(float2*)(C + (size_t)r * N + c0) = make_float2(v0 + rr.x, v1 + rr.y);
                }
            }
        }
    }
}

__global__ void __launch_bounds__(128, 2)
gemm_qkv(const __half* __restrict__ A,
         const __half* __restrict__ wq, const __half* __restrict__ wk,
         const __half* __restrict__ wv,
         __half* __restrict__ q, __half* __restrict__ k, __half* __restrict__ v) {
    const __half* B = (blockIdx.z == 0) ? wq : (blockIdx.z == 1) ? wk : wv;
    __half* Ch = (blockIdx.z == 0) ? q : (blockIdx.z == 1) ? k : v;
    gemm_core(A, B, nullptr, Ch, DD, DD, nullptr, nullptr, 3);
}
__global__ void __launch_bounds__(128, 2)
gemm_f32(const __half* __restrict__ A, const __half* __restrict__ B,
         float* __restrict__ C, int N, int K,
         const float* __restrict__ bias, const float* __restrict__ res) {
    gemm_core(A, B, C, nullptr, N, K, bias, res, 1);
}
__global__ void __launch_bounds__(128, 2)
gemm_gelu(const __half* __restrict__ A, const __half* __restrict__ B,
          __half* __restrict__ Cf, int N, int K, const float* __restrict__ bias) {
    gemm_core(A, B, nullptr, Cf, N, K, bias, nullptr, 2);
}

// ---------------- Flash attention fp16 with mask-skip fast path ----------------
#define AT_STAGE 16384
#define AT_SMEM (16384 + 2 * AT_STAGE)

__global__ void __launch_bounds__(256, 2)
attn_mma_kernel(const __half* __restrict__ q, const __half* __restrict__ k,
                const __half* __restrict__ v, __half* __restrict__ O) {
    extern __shared__ char smem[];
    const uint32_t sb = smem_to_u32(smem);
    const uint32_t sQ = sb;
    const int tid = threadIdx.x, wid = tid >> 5, lane = tid & 31;
    const int qt = blockIdx.x;
    const int h = blockIdx.y & 15, b = blockIdx.y >> 4;
    const size_t rowbase = (size_t)b * SS;
    const int colq = h * HDIM;

    #pragma unroll
    for (int l = 0; l < 4; l++) {
        int f = tid + 256 * l;
        int row = f >> 3, c = f & 7;
        CP_ASYNC16(sQ + swz(row, c * 16),
                   q + (rowbase + qt * 128 + row) * DD + colq + c * 8);
    }
    CP_ASYNC_COMMIT();

    auto load_kv = [&](int kt, int s) {
        uint32_t st = sb + 16384 + s * AT_STAGE;
        #pragma unroll
        for (int l = 0; l < 2; l++) {
            int f = tid + 256 * l;
            int row = f >> 3, c = f & 7;
            size_t g = (rowbase + kt * 64 + row) * DD + colq + c * 8;
            uint32_t o = swz(row, c * 16);
            CP_ASYNC16(st + o,        k + g);
            CP_ASYNC16(st + 8192 + o, v + g);
        }
    };
    load_kv(0, 0);
    CP_ASYNC_COMMIT();

    const int nkt = 2 * qt + 2;
    const int warpq0 = qt * 128 + wid * 16;
    const int ktmax_w = (warpq0 + 15) >> 6;   // last tile this warp touches
    const int ktfull  = warpq0 >> 6;          // tiles < ktfull need no mask
    const int lr = lane & 15, lc = lane >> 4;
    const int r0l = lane >> 2;
    const int c2 = (lane & 3) * 2;
    const int rowg0 = warpq0 + r0l;

    float m_i[2] = {-1e30f, -1e30f}, l_i[2] = {0.f, 0.f};
    float oacc[8][4];
    #pragma unroll
    for (int i = 0; i < 8; i++)
        #pragma unroll
        for (int j = 0; j < 4; j++) oacc[i][j] = 0.f;

    for (int kt = 0; kt < nkt; kt++) {
        if (kt + 1 < nkt) load_kv(kt + 1, (kt + 1) & 1);
        CP_ASYNC_COMMIT();
        CP_ASYNC_WAIT1();
        __syncthreads();

        if (kt <= ktmax_w) {
            uint32_t st = sb + 16384 + (kt & 1) * AT_STAGE;
            uint32_t sK = st, sV = st + 8192;

            float sacc[8][4];
            #pragma unroll
            for (int i = 0; i < 8; i++)
                #pragma unroll
                for (int j = 0; j < 4; j++) sacc[i][j] = 0.f;

            #pragma unroll
            for (int kg = 0; kg < 4; kg++) {
                uint32_t a0[4];
                ldmx4(a0, sQ + swz(wid * 16 + lr, kg * 32 + lc * 16));
                #pragma unroll
                for (int np = 0; np < 4; np++) {
                    uint32_t b4[4];
                    ldmx4(b4, sK + swz(np * 16 + lr, kg * 32 + lc * 16));
                    mma_f16(sacc[np * 2],     a0, b4[0], b4[2]);
                    mma_f16(sacc[np * 2 + 1], a0, b4[1], b4[3]);
                }
            }

            float rm[2] = {-1e30f, -1e30f};
            if (kt >= ktfull) {
                // edge tile: full causal mask
                #pragma unroll
                for (int nt = 0; nt < 8; nt++) {
                    #pragma unroll
                    for (int j = 0; j < 4; j++) {
                        int jr = j >> 1;
                        int rowg = rowg0 + jr * 8;
                        int colg = kt * 64 + nt * 8 + c2 + (j & 1);
                        float s = sacc[nt][j] * 0.125f;
                        if (colg > rowg) s = -1e30f;
                        sacc[nt][j] = s;
                        rm[jr] = fmaxf(rm[jr], s);
                    }
                }
            } else {
                // interior tile: no mask needed
                #pragma unroll
                for (int nt = 0; nt < 8; nt++) {
                    #pragma unroll
                    for (int j = 0; j < 4; j++) {
                        float s = sacc[nt][j] * 0.125f;
                        sacc[nt][j] = s;
                        rm[j >> 1] = fmaxf(rm[j >> 1], s);
                    }
                }
            }
            #pragma unroll
            for (int jr = 0; jr < 2; jr++) {
                rm[jr] = fmaxf(rm[jr], __shfl_xor_sync(0xffffffffu, rm[jr], 1));
                rm[jr] = fmaxf(rm[jr], __shfl_xor_sync(0xffffffffu, rm[jr], 2));
            }
            float sc[2], rs[2] = {0.f, 0.f};
            #pragma unroll
            for (int jr = 0; jr < 2; jr++) {
                float mn = fmaxf(m_i[jr], rm[jr]);
                sc[jr] = __expf(m_i[jr] - mn);
                m_i[jr] = mn;
            }
            #pragma unroll
            for (int nt = 0; nt < 8; nt++) {
                #pragma unroll
                for (int j = 0; j < 4; j++) {
                    float p = __expf(sacc[nt][j] - m_i[j >> 1]);
                    sacc[nt][j] = p;
                    rs[j >> 1] += p;
                }
            }
            #pragma unroll
            for (int jr = 0; jr < 2; jr++) {
                rs[jr] += __shfl_xor_sync(0xffffffffu, rs[jr], 1);
                rs[jr] += __shfl_xor_sync(0xffffffffu, rs[jr], 2);
                l_i[jr] = l_i[jr] * sc[jr] + rs[jr];
            }
            #pragma unroll
            for (int nt = 0; nt < 8; nt++) {
                #pragma unroll
                for (int j = 0; j < 4; j++) oacc[nt][j] *= sc[j >> 1];
            }

            #pragma unroll
            for (int kc = 0; kc < 4; kc++) {
                uint32_t ph[4];
                __half2 p0 = __floats2half2_rn(sacc[2 * kc][0],     sacc[2 * kc][1]);
                __half2 p1 = __floats2half2_rn(sacc[2 * kc][2],     sacc[2 * kc][3]);
                __half2 p2 = __floats2half2_rn(sacc[2 * kc + 1][0], sacc[2 * kc + 1][1]);
                __half2 p3 = __floats2half2_rn(sacc[2 * kc + 1][2], sacc[2 * kc + 1][3]);
                ph[0] = *reinterpret_cast<const uint32_t*>(&p0);
                ph[1] = *reinterpret_cast<const uint32_t*>(&p1);
                ph[2] = *reinterpret_cast<const uint32_t*>(&p2);
                ph[3] = *reinterpret_cast<const uint32_t*>(&p3);
                uint32_t vrow = kc * 16 + ((lane >> 3) & 1) * 8 + (lane & 7);
                #pragma unroll
                for (int dp = 0; dp < 4; dp++) {
                    uint32_t v4[4];
                    ldmx4t(v4, sV + swz(vrow, dp * 32 + (lane >> 4) * 16));
                    mma_f16(oacc[dp * 2],     ph, v4[0], v4[1]);
                    mma_f16(oacc[dp * 2 + 1], ph, v4[2], v4[3]);
                }
            }
        }
        __syncthreads();
    }

    float inv[2] = {1.0f / l_i[0], 1.0f / l_i[1]};
    #pragma unroll
    for (int nt = 0; nt < 8; nt++) {
        #pragma unroll
        for (int jr = 0; jr < 2; jr++) {
            float v0 = oacc[nt][jr * 2 + 0] * inv[jr];
            float v1 = oacc[nt][jr * 2 + 1] * inv[jr];
            __half2 hv = __floats2half2_rn(v0, v1);
            size_t off = (rowbase + rowg0 + jr * 8) * DD + colq + nt * 8 + c2;
            *reinterpret_cast<uint32_t*>(O + off) = *reinterpret_cast<const uint32_t*>(&hv);
        }
    }
}

// ---------------- launch ----------------
extern "C" void kernel_launch(void* const* d_in, const int* in_sizes, int n_in,
                              void* d_out, int out_size) {
    const float* x     = (const float*)d_in[0];
    const float* ln1_g = (const float*)d_in[1];
    const float* ln1_b = (const float*)d_in[2];
    const float* Wq    = (const float*)d_in[3];
    const float* Wk    = (const float*)d_in[4];
    const float* Wv    = (const float*)d_in[5];
    const float* Wo    = (const float*)d_in[6];
    const float* bo    = (const float*)d_in[7];
    const float* ln2_g = (const float*)d_in[8];
    const float* ln2_b = (const float*)d_in[9];
    const float* W1    = (const float*)d_in[10];
    const float* b1    = (const float*)d_in[11];
    const float* W2    = (const float*)d_in[12];
    const float* b2    = (const float*)d_in[13];
    float* out = (float*)d_out;

    float* x2;
    cudaGetSymbolAddress((void**)&x2, g_x2);
    __half *h2, *q, *k, *v, *ctx, *mid;
    cudaGetSymbolAddress((void**)&h2, g_h2);
    cudaGetSymbolAddress((void**)&q, g_q);
    cudaGetSymbolAddress((void**)&k, g_k);
    cudaGetSymbolAddress((void**)&v, g_v);
    cudaGetSymbolAddress((void**)&ctx, g_ctx);
    cudaGetSymbolAddress((void**)&mid, g_mid);

    __half *wq, *wk, *wv, *wo, *w1, *w2;
    cudaGetSymbolAddress((void**)&wq, g_wq);
    cudaGetSymbolAddress((void**)&wk, g_wk);
    cudaGetSymbolAddress((void**)&wv, g_wv);
    cudaGetSymbolAddress((void**)&wo, g_wo);
    cudaGetSymbolAddress((void**)&w1, g_w1);
    cudaGetSymbolAddress((void**)&w2, g_w2);

    static int attr_set = 0;
    if (!attr_set) {
        cudaFuncSetAttribute(attn_mma_kernel, cudaFuncAttributeMaxDynamicSharedMemorySize, AT_SMEM);
        cudaFuncSetAttribute(gemm_qkv,  cudaFuncAttributeMaxDynamicSharedMemorySize, GEMM_SMEM);
        cudaFuncSetAttribute(gemm_f32,  cudaFuncAttributeMaxDynamicSharedMemorySize, GEMM_SMEM);
        cudaFuncSetAttribute(gemm_gelu, cudaFuncAttributeMaxDynamicSharedMemorySize, GEMM_SMEM);
        attr_set = 1;
    }

    const int M = MROWS;

    wsplit_all<<<3072, 256>>>(Wq, Wk, Wv, Wo, W1, W2, wq, wk, wv, wo, w1, w2);

    ln_f16<<<M, 256>>>(x, ln1_g, ln1_b, h2);

    dim3 gQKV(DD / 128, M / 128, 3);
    gemm_qkv<<<gQKV, 128, GEMM_SMEM>>>(h2, wq, wk, wv, q, k, v);

    dim3 gA(SS / 128, BB * HH);
    attn_mma_kernel<<<gA, 256, AT_SMEM>>>(q, k, v, ctx);

    dim3 gDD(DD / 128, M / 128);
    gemm_f32<<<gDD, 128, GEMM_SMEM>>>(ctx, wo, x2, DD, DD, bo, x);

    ln_f16<<<M, 256>>>(x2, ln2_g, ln2_b, h2);

    dim3 gFF(DFF / 128, M / 128);
    gemm_gelu<<<gFF, 128, GEMM_SMEM>>>(h2, w1, mid, DFF, DD, b1);

    gemm_f32<<<gDD, 128, GEMM_SMEM>>>(mid, w2, out, DD, DFF, b2, x2);
}

// round 16
// speedup vs baseline: 1.0481x; 1.0013x over previous
#include <cuda_runtime.h>
#include <cuda_fp16.h>
#include <math.h>
#include <cstdint>

#define BB 2
#define SS 2048
#define DD 1024
#define HH 16
#define HDIM 64
#define DFF 4096
#define MROWS (BB * SS)

// ---------------- PTX helpers ----------------
__device__ __forceinline__ uint32_t smem_to_u32(const void* p) {
    uint32_t a;
    asm("{ .reg .u64 t; cvta.to.shared.u64 t, %1; cvt.u32.u64 %0, t; }" : "=r"(a) : "l"(p));
    return a;
}
__device__ __forceinline__ void ldmx4(uint32_t* r, uint32_t a) {
    asm volatile("ldmatrix.sync.aligned.m8n8.x4.shared.b16 {%0,%1,%2,%3}, [%4];"
        : "=r"(r[0]), "=r"(r[1]), "=r"(r[2]), "=r"(r[3]) : "r"(a));
}
__device__ __forceinline__ void ldmx4t(uint32_t* r, uint32_t a) {
    asm volatile("ldmatrix.sync.aligned.m8n8.x4.trans.shared.b16 {%0,%1,%2,%3}, [%4];"
        : "=r"(r[0]), "=r"(r[1]), "=r"(r[2]), "=r"(r[3]) : "r"(a));
}
__device__ __forceinline__ void mma_f16(float* c, const uint32_t* a, uint32_t b0, uint32_t b1) {
    asm volatile("mma.sync.aligned.m16n8k16.row.col.f32.f16.f16.f32 "
        "{%0,%1,%2,%3}, {%4,%5,%6,%7}, {%8,%9}, {%0,%1,%2,%3};"
        : "+f"(c[0]), "+f"(c[1]), "+f"(c[2]), "+f"(c[3])
        : "r"(a[0]), "r"(a[1]), "r"(a[2]), "r"(a[3]), "r"(b0), "r"(b1));
}
#define CP_ASYNC16(s, g) asm volatile("cp.async.cg.shared.global [%0], [%1], 16;" :: "r"(s), "l"(g))
#define CP_ASYNC_COMMIT() asm volatile("cp.async.commit_group;" ::: "memory")
#define CP_ASYNC_WAIT1()  asm volatile("cp.async.wait_group 1;" ::: "memory")

__device__ __forceinline__ uint32_t swz(uint32_t row, uint32_t colbyte) {
    return row * 128 + (colbyte ^ ((row & 7) << 4));
}
__device__ __forceinline__ float gelu_exact(float v) {
    return 0.5f * v * (1.0f + erff(v * 0.70710678118654752f));
}

// ---------------- scratch ----------------
__device__ float g_x2[MROWS * DD];
__device__ __half g_h2 [MROWS * DD];
__device__ __half g_q  [MROWS * DD];
__device__ __half g_k  [MROWS * DD];
__device__ __half g_v  [MROWS * DD];
__device__ __half g_ctx[MROWS * DD];
__device__ __half g_mid[(size_t)MROWS * DFF];
__device__ __half g_wq[DD * DD], g_wk[DD * DD], g_wv[DD * DD], g_wo[DD * DD];
__device__ __half g_w1[(size_t)DD * DFF], g_w2[(size_t)DFF * DD];

// ---------------- LN row core (fp16 out) ----------------
__device__ __forceinline__ void ln_row(const float* __restrict__ x,
                                       const float* __restrict__ gamma,
                                       const float* __restrict__ beta,
                                       __half* __restrict__ y, int row, int tid) {
    const float4 v = reinterpret_cast<const float4*>(x + (size_t)row * DD)[tid];
    float s = v.x + v.y + v.z + v.w;
    float sq = v.x * v.x + v.y * v.y + v.z * v.z + v.w * v.w;
    for (int o = 16; o > 0; o >>= 1) {
        s += __shfl_down_sync(0xffffffffu, s, o);
        sq += __shfl_down_sync(0xffffffffu, sq, o);
    }
    __shared__ float ws[8], wq[8];
    int lane = tid & 31, warp = tid >> 5;
    if (lane == 0) { ws[warp] = s; wq[warp] = sq; }
    __syncthreads();
    __shared__ float mu_s, rstd_s;
    if (tid == 0) {
        float ts = 0.f, tq = 0.f;
        #pragma unroll
        for (int i = 0; i < 8; i++) { ts += ws[i]; tq += wq[i]; }
        float mu = ts * (1.0f / DD);
        float var = tq * (1.0f / DD) - mu * mu;
        mu_s = mu; rstd_s = rsqrtf(var + 1e-5f);
    }
    __syncthreads();
    float mu = mu_s, r = rstd_s;
    float4 g4 = reinterpret_cast<const float4*>(gamma)[tid];
    float4 b4 = reinterpret_cast<const float4*>(beta)[tid];
    float o0 = (v.x - mu) * r * g4.x + b4.x;
    float o1 = (v.y - mu) * r * g4.y + b4.y;
    float o2 = (v.z - mu) * r * g4.z + b4.z;
    float o3 = (v.w - mu) * r * g4.w + b4.w;
    __half2 h0 = __floats2half2_rn(o0, o1);
    __half2 h1 = __floats2half2_rn(o2, o3);
    uint2 w = make_uint2(*reinterpret_cast<const uint32_t*>(&h0),
                         *reinterpret_cast<const uint32_t*>(&h1));
    *reinterpret_cast<uint2*>(y + (size_t)row * DD + tid * 4) = w;
}

__global__ void ln_f16(const float* __restrict__ x, const float* __restrict__ gamma,
                       const float* __restrict__ beta, __half* __restrict__ y) {
    ln_row(x, gamma, beta, y, blockIdx.x, threadIdx.x);
}

// ---------------- fused prep: weight transpose (3072 blocks) + LN1 (4096 blocks) ----
__global__ void __launch_bounds__(256)
prep_all(const float* __restrict__ Wq, const float* __restrict__ Wk,
         const float* __restrict__ Wv, const float* __restrict__ Wo,
         const float* __restrict__ W1, const float* __restrict__ W2,
         __half* __restrict__ Tq, __half* __restrict__ Tk,
         __half* __restrict__ Tv, __half* __restrict__ To,
         __half* __restrict__ T1, __half* __restrict__ T2,
         const float* __restrict__ x, const float* __restrict__ ln1_g,
         const float* __restrict__ ln1_b, __half* __restrict__ h2) {
    int id = blockIdx.x;
    if (id >= 3072) {                    // LN1 rows
        ln_row(x, ln1_g, ln1_b, h2, id - 3072, threadIdx.x);
        return;
    }
    const float* W; __half* T; int K, N, bx, by;
    if (id < 1024) {
        int wi = id >> 8, rem = id & 255;
        W = (wi == 0) ? Wq : (wi == 1) ? Wk : (wi == 2) ? Wv : Wo;
        T = (wi == 0) ? Tq : (wi == 1) ? Tk : (wi == 2) ? Tv : To;
        K = DD; N = DD; bx = rem & 15; by = rem >> 4;
    } else if (id < 2048) {
        int rem = id - 1024;
        W = W1; T = T1; K = DD; N = DFF; bx = rem & 63; by = rem >> 6;
    } else {
        int rem = id - 2048;
        W = W2; T = T2; K = DFF; N = DD; bx = rem & 15; by = rem >> 4;
    }
    __shared__ float tile[64][65];
    int t = threadIdx.x;
    int tx = t & 15, ty = t >> 4;
    #pragma unroll
    for (int i = 0; i < 4; i++) {
        int row = ty + 16 * i;
        float4 v = *(const float4*)(W + (size_t)(by * 64 + row) * N + bx * 64 + tx * 4);
        tile[row][tx * 4 + 0] = v.x;
        tile[row][tx * 4 + 1] = v.y;
        tile[row][tx * 4 + 2] = v.z;
        tile[row][tx * 4 + 3] = v.w;
    }
    __syncthreads();
    #pragma unroll
    for (int i = 0; i < 4; i++) {
        int n = ty + 16 * i;
        __half2 h0 = __floats2half2_rn(tile[tx * 4 + 0][n], tile[tx * 4 + 1][n]);
        __half2 h1 = __floats2half2_rn(tile[tx * 4 + 2][n], tile[tx * 4 + 3][n]);
        uint2 w = make_uint2(*reinterpret_cast<const uint32_t*>(&h0),
                             *reinterpret_cast<const uint32_t*>(&h1));
        *reinterpret_cast<uint2*>(T + (size_t)(bx * 64 + n) * K + by * 64 + tx * 4) = w;
    }
}

// ---------------- GEMM core (4 warps, 64x64 warp tile, frag pipe) ----------------
__device__ __forceinline__ void cpa_tile(uint32_t sdst, const __half* __restrict__ g,
                                         int K, int r0, int k0, int tid) {
    #pragma unroll
    for (int l = 0; l < 8; l++) {
        int f = tid + 128 * l;
        int row = f >> 3, c = f & 7;
        CP_ASYNC16(sdst + swz(row, c * 16), g + (size_t)(r0 + row) * K + k0 + c * 8);
    }
}

#define STAGE1 (2 * 16384)
#define GEMM_SMEM (3 * STAGE1)

__device__ __forceinline__ void gemm_core(const __half* __restrict__ A,
                                          const __half* __restrict__ B,
                                          float* __restrict__ C,
                                          __half* __restrict__ Ch,
                                          int N, int K,
                                          const float* __restrict__ bias,
                                          const float* __restrict__ res, int mode) {
    extern __shared__ char smem[];
    const uint32_t sb0 = smem_to_u32(smem);
    const int tid = threadIdx.x;
    const int wid = tid >> 5, lane = tid & 31;
    const int wm = wid >> 1, wn = wid & 1;
    const int m0 = blockIdx.y * 128, n0 = blockIdx.x * 128;
    const int lr = lane & 15, lc = lane >> 4;

    float acc[4][8][4];
    #pragma unroll
    for (int i = 0; i < 4; i++)
        #pragma unroll
        for (int j = 0; j < 8; j++)
            #pragma unroll
            for (int p = 0; p < 4; p++) acc[i][j][p] = 0.f;

    const int T = K >> 6;
    auto load_tile = [&](int t, int s) {
        uint32_t sb = sb0 + s * STAGE1;
        int k0 = t * 64;
        cpa_tile(sb,         A, K, m0, k0, tid);
        cpa_tile(sb + 16384, B, K, n0, k0, tid);
    };

    load_tile(0, 0);
    CP_ASYNC_COMMIT();
    load_tile(1, 1);
    CP_ASYNC_COMMIT();

    uint32_t af[2][4][4], bf[2][4][4];

    for (int t = 0; t < T; t++) {
        CP_ASYNC_WAIT1();
        __syncthreads();
        if (t + 2 < T) { load_tile(t + 2, (t + 2) % 3); CP_ASYNC_COMMIT(); }

        const uint32_t sb = sb0 + (t % 3) * STAGE1;
        const uint32_t sA = sb, sB = sb + 16384;

        #pragma unroll
        for (int mt = 0; mt < 4; mt++)
            ldmx4(af[0][mt], sA + swz(wm * 64 + mt * 16 + lr, lc * 16));
        #pragma unroll
        for (int np = 0; np < 4; np++)
            ldmx4(bf[0][np], sB + swz(wn * 64 + np * 16 + lr, lc * 16));

        #pragma unroll
        for (int kg = 0; kg < 4; kg++) {
            const int cur = kg & 1, nxt = cur ^ 1;
            if (kg < 3) {
                #pragma unroll
                for (int mt = 0; mt < 4; mt++)
                    ldmx4(af[nxt][mt], sA + swz(wm * 64 + mt * 16 + lr, (kg + 1) * 32 + lc * 16));
                #pragma unroll
                for (int np = 0; np < 4; np++)
                    ldmx4(bf[nxt][np], sB + swz(wn * 64 + np * 16 + lr, (kg + 1) * 32 + lc * 16));
            }
            #pragma unroll
            for (int mt = 0; mt < 4; mt++) {
                #pragma unroll
                for (int np = 0; np < 4; np++) {
                    mma_f16(acc[mt][np * 2 + 0], af[cur][mt], bf[cur][np][0], bf[cur][np][2]);
                    mma_f16(acc[mt][np * 2 + 1], af[cur][mt], bf[cur][np][1], bf[cur][np][3]);
                }
            }
        }
    }

    #pragma unroll
    for (int mt = 0; mt < 4; mt++) {
        #pragma unroll
        for (int nt = 0; nt < 8; nt++) {
            int r0 = m0 + wm * 64 + mt * 16 + (lane >> 2);
            int c0 = n0 + wn * 64 + nt * 8 + (lane & 3) * 2;
            float bv0 = 0.f, bv1 = 0.f;
            if (mode == 1 || mode == 2) { bv0 = bias[c0]; bv1 = bias[c0 + 1]; }
            #pragma unroll
            for (int half = 0; half < 2; half++) {
                int r = r0 + half * 8;
                float v0 = acc[mt][nt][half * 2 + 0] + bv0;
                float v1 = acc[mt][nt][half * 2 + 1] + bv1;
                if (mode == 3) {
                    __half2 hv = __floats2half2_rn(v0, v1);
                    *reinterpret_cast<uint32_t*>(Ch + (size_t)r * N + c0) =
                        *reinterpret_cast<const uint32_t*>(&hv);
                } else if (mode == 2) {
                    v0 = gelu_exact(v0); v1 = gelu_exact(v1);
                    __half2 hv = __floats2half2_rn(v0, v1);
                    *reinterpret_cast<uint32_t*>(Ch + (size_t)r * N + c0) =
                        *reinterpret_cast<const uint32_t*>(&hv);
                } else {
                    float2 rr = *(const float2*)(res + (size_t)r * N + c0);
                    *(float2*)(C + (size_t)r * N + c0) = make_float2(v0 + rr.x, v1 + rr.y);
                }
            }
        }
    }
}

__global__ void __launch_bounds__(128, 2)
gemm_qkv(const __half* __restrict__ A,
         const __half* __restrict__ wq, const __half* __restrict__ wk,
         const __half* __restrict__ wv,
         __half* __restrict__ q, __half* __restrict__ k, __half* __restrict__ v) {
    const __half* B = (blockIdx.z == 0) ? wq : (blockIdx.z == 1) ? wk : wv;
    __half* Ch = (blockIdx.z == 0) ? q : (blockIdx.z == 1) ? k : v;
    gemm_core(A, B, nullptr, Ch, DD, DD, nullptr, nullptr, 3);
}
__global__ void __launch_bounds__(128, 2)
gemm_f32(const __half* __restrict__ A, const __half* __restrict__ B,
         float* __restrict__ C, int N, int K,
         const float* __restrict__ bias, const float* __restrict__ res) {
    gemm_core(A, B, C, nullptr, N, K, bias, res, 1);
}
__global__ void __launch_bounds__(128, 2)
gemm_gelu(const __half* __restrict__ A, const __half* __restrict__ B,
          __half* __restrict__ Cf, int N, int K, const float* __restrict__ bias) {
    gemm_core(A, B, nullptr, Cf, N, K, bias, nullptr, 2);
}

// ---------------- Flash attention fp16, mask-skip + big-first scheduling ------------
#define AT_STAGE 16384
#define AT_SMEM (16384 + 2 * AT_STAGE)

__global__ void __launch_bounds__(256, 2)
attn_mma_kernel(const __half* __restrict__ q, const __half* __restrict__ k,
                const __half* __restrict__ v, __half* __restrict__ O) {
    extern __shared__ char smem[];
    const uint32_t sb = smem_to_u32(smem);
    const uint32_t sQ = sb;
    const int tid = threadIdx.x, wid = tid >> 5, lane = tid & 31;
    const int qt = (int)(gridDim.x - 1 - blockIdx.x);   // largest q-tile first
    const int h = blockIdx.y & 15, b = blockIdx.y >> 4;
    const size_t rowbase = (size_t)b * SS;
    const int colq = h * HDIM;

    #pragma unroll
    for (int l = 0; l < 4; l++) {
        int f = tid + 256 * l;
        int row = f >> 3, c = f & 7;
        CP_ASYNC16(sQ + swz(row, c * 16),
                   q + (rowbase + qt * 128 + row) * DD + colq + c * 8);
    }
    CP_ASYNC_COMMIT();

    auto load_kv = [&](int kt, int s) {
        uint32_t st = sb + 16384 + s * AT_STAGE;
        #pragma unroll
        for (int l = 0; l < 2; l++) {
            int f = tid + 256 * l;
            int row = f >> 3, c = f & 7;
            size_t g = (rowbase + kt * 64 + row) * DD + colq + c * 8;
            uint32_t o = swz(row, c * 16);
            CP_ASYNC16(st + o,        k + g);
            CP_ASYNC16(st + 8192 + o, v + g);
        }
    };
    load_kv(0, 0);
    CP_ASYNC_COMMIT();

    const int nkt = 2 * qt + 2;
    const int warpq0 = qt * 128 + wid * 16;
    const int ktmax_w = (warpq0 + 15) >> 6;
    const int ktfull  = warpq0 >> 6;
    const int lr = lane & 15, lc = lane >> 4;
    const int r0l = lane >> 2;
    const int c2 = (lane & 3) * 2;
    const int rowg0 = warpq0 + r0l;

    float m_i[2] = {-1e30f, -1e30f}, l_i[2] = {0.f, 0.f};
    float oacc[8][4];
    #pragma unroll
    for (int i = 0; i < 8; i++)
        #pragma unroll
        for (int j = 0; j < 4; j++) oacc[i][j] = 0.f;

    for (int kt = 0; kt < nkt; kt++) {
        if (kt + 1 < nkt) load_kv(kt + 1, (kt + 1) & 1);
        CP_ASYNC_COMMIT();
        CP_ASYNC_WAIT1();
        __syncthreads();

        if (kt <= ktmax_w) {
            uint32_t st = sb + 16384 + (kt & 1) * AT_STAGE;
            uint32_t sK = st, sV = st + 8192;

            float sacc[8][4];
            #pragma unroll
            for (int i = 0; i < 8; i++)
                #pragma unroll
                for (int j = 0; j < 4; j++) sacc[i][j] = 0.f;

            #pragma unroll
            for (int kg = 0; kg < 4; kg++) {
                uint32_t a0[4];
                ldmx4(a0, sQ + swz(wid * 16 + lr, kg * 32 + lc * 16));
                #pragma unroll
                for (int np = 0; np < 4; np++) {
                    uint32_t b4[4];
                    ldmx4(b4, sK + swz(np * 16 + lr, kg * 32 + lc * 16));
                    mma_f16(sacc[np * 2],     a0, b4[0], b4[2]);
                    mma_f16(sacc[np * 2 + 1], a0, b4[1], b4[3]);
                }
            }

            float rm[2] = {-1e30f, -1e30f};
            if (kt >= ktfull) {
                #pragma unroll
                for (int nt = 0; nt < 8; nt++) {
                    #pragma unroll
                    for (int j = 0; j < 4; j++) {
                        int jr = j >> 1;
                        int rowg = rowg0 + jr * 8;
                        int colg = kt * 64 + nt * 8 + c2 + (j & 1);
                        float s = sacc[nt][j] * 0.125f;
                        if (colg > rowg) s = -1e30f;
                        sacc[nt][j] = s;
                        rm[jr] = fmaxf(rm[jr], s);
                    }
                }
            } else {
                #pragma unroll
                for (int nt = 0; nt < 8; nt++) {
                    #pragma unroll
                    for (int j = 0; j < 4; j++) {
                        float s = sacc[nt][j] * 0.125f;
                        sacc[nt][j] = s;
                        rm[j >> 1] = fmaxf(rm[j >> 1], s);
                    }
                }
            }
            #pragma unroll
            for (int jr = 0; jr < 2; jr++) {
                rm[jr] = fmaxf(rm[jr], __shfl_xor_sync(0xffffffffu, rm[jr], 1));
                rm[jr] = fmaxf(rm[jr], __shfl_xor_sync(0xffffffffu, rm[jr], 2));
            }
            float sc[2], rs[2] = {0.f, 0.f};
            #pragma unroll
            for (int jr = 0; jr < 2; jr++) {
                float mn = fmaxf(m_i[jr], rm[jr]);
                sc[jr] = __expf(m_i[jr] - mn);
                m_i[jr] = mn;
            }
            #pragma unroll
            for (int nt = 0; nt < 8; nt++) {
                #pragma unroll
                for (int j = 0; j < 4; j++) {
                    float p = __expf(sacc[nt][j] - m_i[j >> 1]);
                    sacc[nt][j] = p;
                    rs[j >> 1] += p;
                }
            }
            #pragma unroll
            for (int jr = 0; jr < 2; jr++) {
                rs[jr] += __shfl_xor_sync(0xffffffffu, rs[jr], 1);
                rs[jr] += __shfl_xor_sync(0xffffffffu, rs[jr], 2);
                l_i[jr] = l_i[jr] * sc[jr] + rs[jr];
            }
            #pragma unroll
            for (int nt = 0; nt < 8; nt++) {
                #pragma unroll
                for (int j = 0; j < 4; j++) oacc[nt][j] *= sc[j >> 1];
            }

            #pragma unroll
            for (int kc = 0; kc < 4; kc++) {
                uint32_t ph[4];
                __half2 p0 = __floats2half2_rn(sacc[2 * kc][0],     sacc[2 * kc][1]);
                __half2 p1 = __floats2half2_rn(sacc[2 * kc][2],     sacc[2 * kc][3]);
                __half2 p2 = __floats2half2_rn(sacc[2 * kc + 1][0], sacc[2 * kc + 1][1]);
                __half2 p3 = __floats2half2_rn(sacc[2 * kc + 1][2], sacc[2 * kc + 1][3]);
                ph[0] = *reinterpret_cast<const uint32_t*>(&p0);
                ph[1] = *reinterpret_cast<const uint32_t*>(&p1);
                ph[2] = *reinterpret_cast<const uint32_t*>(&p2);
                ph[3] = *reinterpret_cast<const uint32_t*>(&p3);
                uint32_t vrow = kc * 16 + ((lane >> 3) & 1) * 8 + (lane & 7);
                #pragma unroll
                for (int dp = 0; dp < 4; dp++) {
                    uint32_t v4[4];
                    ldmx4t(v4, sV + swz(vrow, dp * 32 + (lane >> 4) * 16));
                    mma_f16(oacc[dp * 2],     ph, v4[0], v4[1]);
                    mma_f16(oacc[dp * 2 + 1], ph, v4[2], v4[3]);
                }
            }
        }
        __syncthreads();
    }

    float inv[2] = {1.0f / l_i[0], 1.0f / l_i[1]};
    #pragma unroll
    for (int nt = 0; nt < 8; nt++) {
        #pragma unroll
        for (int jr = 0; jr < 2; jr++) {
            float v0 = oacc[nt][jr * 2 + 0] * inv[jr];
            float v1 = oacc[nt][jr * 2 + 1] * inv[jr];
            __half2 hv = __floats2half2_rn(v0, v1);
            size_t off = (rowbase + rowg0 + jr * 8) * DD + colq + nt * 8 + c2;
            *reinterpret_cast<uint32_t*>(O + off) = *reinterpret_cast<const uint32_t*>(&hv);
        }
    }
}

// ---------------- launch ----------------
extern "C" void kernel_launch(void* const* d_in, const int* in_sizes, int n_in,
                              void* d_out, int out_size) {
    const float* x     = (const float*)d_in[0];
    const float* ln1_g = (const float*)d_in[1];
    const float* ln1_b = (const float*)d_in[2];
    const float* Wq    = (const float*)d_in[3];
    const float* Wk    = (const float*)d_in[4];
    const float* Wv    = (const float*)d_in[5];
    const float* Wo    = (const float*)d_in[6];
    const float* bo    = (const float*)d_in[7];
    const float* ln2_g = (const float*)d_in[8];
    const float* ln2_b = (const float*)d_in[9];
    const float* W1    = (const float*)d_in[10];
    const float* b1    = (const float*)d_in[11];
    const float* W2    = (const float*)d_in[12];
    const float* b2    = (const float*)d_in[13];
    float* out = (float*)d_out;

    float* x2;
    cudaGetSymbolAddress((void**)&x2, g_x2);
    __half *h2, *q, *k, *v, *ctx, *mid;
    cudaGetSymbolAddress((void**)&h2, g_h2);
    cudaGetSymbolAddress((void**)&q, g_q);
    cudaGetSymbolAddress((void**)&k, g_k);
    cudaGetSymbolAddress((void**)&v, g_v);
    cudaGetSymbolAddress((void**)&ctx, g_ctx);
    cudaGetSymbolAddress((void**)&mid, g_mid);

    __half *wq, *wk, *wv, *wo, *w1, *w2;
    cudaGetSymbolAddress((void**)&wq, g_wq);
    cudaGetSymbolAddress((void**)&wk, g_wk);
    cudaGetSymbolAddress((void**)&wv, g_wv);
    cudaGetSymbolAddress((void**)&wo, g_wo);
    cudaGetSymbolAddress((void**)&w1, g_w1);
    cudaGetSymbolAddress((void**)&w2, g_w2);

    static int attr_set = 0;
    if (!attr_set) {
        cudaFuncSetAttribute(attn_mma_kernel, cudaFuncAttributeMaxDynamicSharedMemorySize, AT_SMEM);
        cudaFuncSetAttribute(gemm_qkv,  cudaFuncAttributeMaxDynamicSharedMemorySize, GEMM_SMEM);
        cudaFuncSetAttribute(gemm_f32,  cudaFuncAttributeMaxDynamicSharedMemorySize, GEMM_SMEM);
        cudaFuncSetAttribute(gemm_gelu, cudaFuncAttributeMaxDynamicSharedMemorySize, GEMM_SMEM);
        attr_set = 1;
    }

    const int M = MROWS;

    // 1. weight transposes + LN1 fused in one launch
    prep_all<<<3072 + M, 256>>>(Wq, Wk, Wv, Wo, W1, W2, wq, wk, wv, wo, w1, w2,
                                x, ln1_g, ln1_b, h2);

    // 2. QKV
    dim3 gQKV(DD / 128, M / 128, 3);
    gemm_qkv<<<gQKV, 128, GEMM_SMEM>>>(h2, wq, wk, wv, q, k, v);

    // 3. attention (big-first)
    dim3 gA(SS / 128, BB * HH);
    attn_mma_kernel<<<gA, 256, AT_SMEM>>>(q, k, v, ctx);

    // 4. Wo + bias + residual
    dim3 gDD(DD / 128, M / 128);
    gemm_f32<<<gDD, 128, GEMM_SMEM>>>(ctx, wo, x2, DD, DD, bo, x);

    // 5. LN2
    ln_f16<<<M, 256>>>(x2, ln2_g, ln2_b, h2);

    // 6. MLP1 + GELU
    dim3 gFF(DFF / 128, M / 128);
    gemm_gelu<<<gFF, 128, GEMM_SMEM>>>(h2, w1, mid, DFF, DD, b1);

    // 7. MLP2 + bias + residual
    gemm_f32<<<gDD, 128, GEMM_SMEM>>>(mid, w2, out, DD, DFF, b2, x2);
}